// round 2
// baseline (speedup 1.0000x reference)
#include <cuda_runtime.h>

namespace {
constexpr int Hn = 1024;   // time steps

__device__ __forceinline__ float tanh_fast(float x){ float r; asm("tanh.approx.f32 %0, %1;" : "=f"(r) : "f"(x)); return r; }
__device__ __forceinline__ float ex2_fast (float x){ float r; asm("ex2.approx.ftz.f32 %0, %1;" : "=f"(r) : "f"(x)); return r; }
__device__ __forceinline__ float lg2_fast (float x){ float r; asm("lg2.approx.ftz.f32 %0, %1;" : "=f"(r) : "f"(x)); return r; }
__device__ __forceinline__ float rcp_fast (float x){ float r; asm("rcp.approx.ftz.f32 %0, %1;" : "=f"(r) : "f"(x)); return r; }
// softplus given pre-scaled (log2e) argument: log2(1 + 2^y)
__device__ __forceinline__ float sp_pre(float y){ return lg2_fast(1.0f + ex2_fast(y)); }
}

// 2 batteries per warp; 16 lanes per battery. Lane g owns hp units {g+16k, k<8}
// and hr units {g+16k, k<4}. Critical Q-reduce: 16 parallel shfl.idx gathers
// (uniform source order -> bit-identical sums in every lane) + add tree.
// Off-critical reduces: butterfly (latency hidden under the Q chain).
__global__ void __launch_bounds__(128, 1) dci_rollout(
    const float* __restrict__ gI, const float* __restrict__ gT, const float* __restrict__ soc0,
    const float* __restrict__ W1p, const float* __restrict__ b1p,
    const float* __restrict__ W2p, const float* __restrict__ b2p,
    const float* __restrict__ W1r, const float* __restrict__ b1r,
    const float* __restrict__ W2r, const float* __restrict__ b2r,
    float* __restrict__ out)
{
    const int tid  = blockIdx.x * blockDim.x + threadIdx.x;
    const int lane = threadIdx.x & 31;
    const int g    = lane & 15;
    const int half = lane & 16;
    const int bat  = (tid >> 5) * 2 + (lane >> 4);

    constexpr float LOG2E = 1.4426950408889634f;
    constexpr float LN2   = 0.6931471805599453f;
    constexpr float EPS   = 1e-6f;

    // --- weights into registers (one-time); W2 columns pre-scaled by log2e ---
    float w0[8], w1[8], w2[8], wb[8];
    float wx[8], wy[8], wz[8], wq[8];
#pragma unroll
    for (int k = 0; k < 8; ++k) {
        int u = g + 16 * k;
        w0[k] = W1p[u]; w1[k] = W1p[128 + u]; w2[k] = W1p[256 + u]; wb[k] = b1p[u];
        float4 wp = reinterpret_cast<const float4*>(W2p)[u];   // [R0,R1,C1,Q] row u
        wx[k] = wp.x * LOG2E; wy[k] = wp.y * LOG2E; wz[k] = wp.z * LOG2E; wq[k] = wp.w * LOG2E;
    }
    float q0[4], q1[4], q2[4], qb[4], qw[4];
#pragma unroll
    for (int k = 0; k < 4; ++k) {
        int u = g + 16 * k;
        q0[k] = W1r[u]; q1[k] = W1r[64 + u]; q2[k] = W1r[128 + u]; qb[k] = b1r[u];
        qw[k] = W2r[u];
    }
    float4 b2 = *reinterpret_cast<const float4*>(b2p);
    // biases pre-scaled by log2e and divided by 16 (folded into each lane's partial)
    const float bx16 = b2.x * (LOG2E / 16.0f);
    const float by16 = b2.y * (LOG2E / 16.0f);
    const float bz16 = b2.z * (LOG2E / 16.0f);
    const float bq16 = b2.w * (LOG2E / 16.0f);
    const float br   = b2r[0];

    float s0  = soc0[bat];
    float soc = (s0 == s0) ? s0 : 0.8f;   // NaN -> 0.8
    float v1  = 0.0f;

    const float* Ib = gI + bat * Hn;
    const float* Tb = gT + bat * Hn;
    float It  = __ldg(Ib), Tt = __ldg(Tb);
    float cIt = It * (-1.0f / 3600.0f);
    float vkeep = 0.0f;
    float* orow = out + bat * Hn;

#pragma unroll 1
    for (int t = 0; t < Hn; ++t) {
        const int tn = (t + 1 < Hn) ? (t + 1) : (Hn - 1);
        const float In = __ldg(Ib + tn);
        const float Tn = __ldg(Tb + tn);

        // hp hidden layer (critical): issue these 8 tanhs FIRST
        float h[8];
#pragma unroll
        for (int k = 0; k < 8; ++k) {
            float pre = fmaf(It, w1[k], fmaf(Tt, w2[k], wb[k]));
            h[k] = tanh_fast(fmaf(soc, w0[k], pre));
        }
        // hr hidden layer (off-critical) — MUFU slots fill the gather-wait
        float hr[4];
#pragma unroll
        for (int k = 0; k < 4; ++k) {
            float pre = fmaf(It, q1[k], fmaf(Tt, q2[k], qb[k]));
            hr[k] = tanh_fast(fmaf(soc, q0[k], pre));
        }

        // --- critical: Q partial (tree) -> 16-way gather -> softplus -> soc ---
        float t0 = fmaf(h[0], wq[0], bq16);
        float t1 = h[1] * wq[1];
        float t2 = h[2] * wq[2];
        float t3 = h[3] * wq[3];
        float t4 = h[4] * wq[4];
        float t5 = h[5] * wq[5];
        float t6 = h[6] * wq[6];
        float t7 = h[7] * wq[7];
        float p3 = ((t0 + t1) + (t2 + t3)) + ((t4 + t5) + (t6 + t7));

        float r[16];
#pragma unroll
        for (int j = 0; j < 16; ++j)
            r[j] = __shfl_sync(0xffffffffu, p3, half | j);
        float s3 = (((r[0] + r[1]) + (r[2] + r[3])) + ((r[4] + r[5]) + (r[6] + r[7])))
                 + (((r[8] + r[9]) + (r[10] + r[11])) + ((r[12] + r[13]) + (r[14] + r[15])));

        float Q    = fmaf(sp_pre(s3), 5.0f * LN2, EPS);
        float rq   = rcp_fast(Q);
        float socn = __saturatef(fmaf(cIt, rq, soc));

        // --- off-critical: R0/R1/C1 partials (butterfly), resid, v1, output ---
        float p0 = fmaf(h[0], wx[0], bx16);
        float p1 = fmaf(h[0], wy[0], by16);
        float p2 = fmaf(h[0], wz[0], bz16);
#pragma unroll
        for (int k = 1; k < 8; ++k) {
            p0 = fmaf(h[k], wx[k], p0);
            p1 = fmaf(h[k], wy[k], p1);
            p2 = fmaf(h[k], wz[k], p2);
        }
        float pr = hr[0] * qw[0];
#pragma unroll
        for (int k = 1; k < 4; ++k) pr = fmaf(hr[k], qw[k], pr);
#pragma unroll
        for (int d = 1; d <= 8; d <<= 1) {
            p0 += __shfl_xor_sync(0xffffffffu, p0, d);
            p1 += __shfl_xor_sync(0xffffffffu, p1, d);
            p2 += __shfl_xor_sync(0xffffffffu, p2, d);
            pr += __shfl_xor_sync(0xffffffffu, pr, d);
        }
        float R0 = fmaf(sp_pre(p0), 0.01f   * LN2, EPS);
        float R1 = fmaf(sp_pre(p1), 0.02f   * LN2, EPS);
        float C1 = fmaf(sp_pre(p2), 2000.0f * LN2, EPS);
        float resid = pr + br;

        float invRC = rcp_fast(R1 * C1);
        float invC1 = invRC * R1;                            // 1/C1 = R1/(R1*C1)
        float v1n = fmaf(It, invC1, fmaf(-v1, invRC, v1));   // v1 - v1/(R1C1) + I/C1

        float ocv = fmaf(fmaf(fmaf(0.3f, socn, -0.5f), socn, 1.2f), socn, 3.0f);
        float Vp  = (ocv - fmaf(It, R0, v1n)) + resid;       // ocv - I*R0 - v1 + resid

        // buffer one value per lane; coalesced 16-wide row store every 16 steps
        if ((t & 15) == g)  vkeep = Vp;
        if ((t & 15) == 15) orow[(t & ~15) + g] = vkeep;

        soc = socn; v1 = v1n;
        It = In; Tt = Tn; cIt = In * (-1.0f / 3600.0f);
    }
}

extern "C" void kernel_launch(void* const* d_in, const int* in_sizes, int n_in,
                              void* d_out, int out_size)
{
    // inputs: V(unused), I, Tz, soc0, W1p, b1p, W2p, b2p, W1r, b1r, W2r, b2r
    const float* I    = (const float*)d_in[1];
    const float* Tz   = (const float*)d_in[2];
    const float* soc0 = (const float*)d_in[3];
    const float* W1p  = (const float*)d_in[4];
    const float* b1p  = (const float*)d_in[5];
    const float* W2p  = (const float*)d_in[6];
    const float* b2p  = (const float*)d_in[7];
    const float* W1r  = (const float*)d_in[8];
    const float* b1r  = (const float*)d_in[9];
    const float* W2r  = (const float*)d_in[10];
    const float* b2r  = (const float*)d_in[11];
    float* out = (float*)d_out;

    // 512 warps = 1024 batteries (2/warp); 128 blocks x 128 threads
    // -> 1 block/SM, exactly 1 warp per SMSP (no MUFU collision).
    dci_rollout<<<128, 128>>>(I, Tz, soc0, W1p, b1p, W2p, b2p,
                              W1r, b1r, W2r, b2r, out);
}

// round 4
// speedup vs baseline: 1.0054x; 1.0054x over previous
#include <cuda_runtime.h>

namespace {
constexpr int Hn = 1024;   // time steps

__device__ __forceinline__ float tanh_fast(float x){ float r; asm("tanh.approx.f32 %0, %1;" : "=f"(r) : "f"(x)); return r; }
__device__ __forceinline__ float ex2_fast (float x){ float r; asm("ex2.approx.ftz.f32 %0, %1;" : "=f"(r) : "f"(x)); return r; }
__device__ __forceinline__ float lg2_fast (float x){ float r; asm("lg2.approx.ftz.f32 %0, %1;" : "=f"(r) : "f"(x)); return r; }
__device__ __forceinline__ float rcp_fast (float x){ float r; asm("rcp.approx.ftz.f32 %0, %1;" : "=f"(r) : "f"(x)); return r; }
// softplus given pre-scaled (log2e) argument: log2(1 + 2^y)
__device__ __forceinline__ float sp_pre(float y){ return lg2_fast(1.0f + ex2_fast(y)); }
}

// 2 batteries per warp; 16 lanes per battery. Lane g owns hp units {g+16k, k<8},
// hr units {g+16k, k<4}. Software-pipelined: iteration t runs the critical soc
// chain for step t interleaved with the (independent) V_pred work of step t-1.
__global__ void __launch_bounds__(128, 1) dci_rollout(
    const float* __restrict__ gI, const float* __restrict__ gT, const float* __restrict__ soc0,
    const float* __restrict__ W1p, const float* __restrict__ b1p,
    const float* __restrict__ W2p, const float* __restrict__ b2p,
    const float* __restrict__ W1r, const float* __restrict__ b1r,
    const float* __restrict__ W2r, const float* __restrict__ b2r,
    float* __restrict__ out)
{
    const int tid  = blockIdx.x * blockDim.x + threadIdx.x;
    const int lane = threadIdx.x & 31;
    const int g    = lane & 15;
    const int half = lane & 16;
    const int bat  = (tid >> 5) * 2 + (lane >> 4);

    constexpr float LOG2E = 1.4426950408889634f;
    constexpr float LN2   = 0.6931471805599453f;
    constexpr float EPS   = 1e-6f;

    // --- weights into registers (one-time); W2 columns pre-scaled by log2e ---
    float w0[8], w1[8], w2[8], wb[8];
    float wx[8], wy[8], wz[8], wq[8];
#pragma unroll
    for (int k = 0; k < 8; ++k) {
        int u = g + 16 * k;
        w0[k] = W1p[u]; w1[k] = W1p[128 + u]; w2[k] = W1p[256 + u]; wb[k] = b1p[u];
        float4 wp = reinterpret_cast<const float4*>(W2p)[u];   // [R0,R1,C1,Q] row u
        wx[k] = wp.x * LOG2E; wy[k] = wp.y * LOG2E; wz[k] = wp.z * LOG2E; wq[k] = wp.w * LOG2E;
    }
    float q0[4], q1[4], q2[4], qb[4], qw[4];
#pragma unroll
    for (int k = 0; k < 4; ++k) {
        int u = g + 16 * k;
        q0[k] = W1r[u]; q1[k] = W1r[64 + u]; q2[k] = W1r[128 + u]; qb[k] = b1r[u];
        qw[k] = W2r[u];
    }
    float4 b2 = *reinterpret_cast<const float4*>(b2p);
    // biases pre-scaled by log2e, divided by 16 (folded into each lane's partial)
    const float bx16 = b2.x * (LOG2E / 16.0f);
    const float by16 = b2.y * (LOG2E / 16.0f);
    const float bz16 = b2.z * (LOG2E / 16.0f);
    const float bq16 = b2.w * (LOG2E / 16.0f);
    const float br16 = b2r[0] * (1.0f / 16.0f);

    float s0  = soc0[bat];
    float soc = (s0 == s0) ? s0 : 0.8f;   // NaN -> 0.8
    float v1  = 0.0f;

    const float* Ib = gI + bat * Hn;
    const float* Tb = gT + bat * Hn;
    float It  = __ldg(Ib), Tt = __ldg(Tb);
    float cIt = It * (-1.0f / 3600.0f);
    float vkeep = 0.0f;
    float* orow = out + bat * Hn;

    // pipelined previous-step state (t = -1 dummy: h=0, I=0 -> v1 update is a
    // no-op; the garbage Vp it buffers into lane 15 is overwritten at t=15
    // before the first store at t=15's flush)
    float h[8];
#pragma unroll
    for (int k = 0; k < 8; ++k) h[k] = 0.0f;
    float socInP = 0.0f, IP = 0.0f, TP = 0.0f;

#pragma unroll 1
    for (int t = 0; t < Hn; ++t) {
        const int tn = (t + 1 < Hn) ? (t + 1) : (Hn - 1);
        const float In = __ldg(Ib + tn);
        const float Tn = __ldg(Tb + tn);

        // ================= deferred: V_pred for step t-1 =================
        // Independent of this step's critical chain (fills its stall windows).
        // Uses: h[] (step t-1 hidden), socInP/IP/TP (step t-1 inputs),
        //       soc (== socn of step t-1), v1.
        float p0 = fmaf(h[0], wx[0], bx16);
        float p1 = fmaf(h[0], wy[0], by16);
        float p2 = fmaf(h[0], wz[0], bz16);
#pragma unroll
        for (int k = 1; k < 8; ++k) {
            p0 = fmaf(h[k], wx[k], p0);
            p1 = fmaf(h[k], wy[k], p1);
            p2 = fmaf(h[k], wz[k], p2);
        }
        float pr = br16;
#pragma unroll
        for (int k = 0; k < 4; ++k) {
            float pre = fmaf(IP, q1[k], fmaf(TP, q2[k], qb[k]));
            float hrk = tanh_fast(fmaf(socInP, q0[k], pre));
            pr = fmaf(hrk, qw[k], pr);
        }
#pragma unroll
        for (int d = 1; d <= 8; d <<= 1) {
            p0 += __shfl_xor_sync(0xffffffffu, p0, d);
            p1 += __shfl_xor_sync(0xffffffffu, p1, d);
            p2 += __shfl_xor_sync(0xffffffffu, p2, d);
            pr += __shfl_xor_sync(0xffffffffu, pr, d);
        }
        float R0 = fmaf(sp_pre(p0), 0.01f   * LN2, EPS);
        float R1 = fmaf(sp_pre(p1), 0.02f   * LN2, EPS);
        float C1 = fmaf(sp_pre(p2), 2000.0f * LN2, EPS);

        float invRC = rcp_fast(R1 * C1);
        float invC1 = invRC * R1;                            // 1/C1 = R1/(R1*C1)
        float v1n = fmaf(IP, invC1, fmaf(-v1, invRC, v1));   // v1 - v1/(R1C1) + I/C1

        float ocv = fmaf(fmaf(fmaf(0.3f, soc, -0.5f), soc, 1.2f), soc, 3.0f);
        float Vp  = (ocv - fmaf(IP, R0, v1n)) + pr;          // ocv - I*R0 - v1 + resid

        const int tp = t - 1;
        if ((tp & 15) == g)  vkeep = Vp;
        if ((tp & 15) == 15) orow[(tp & ~15) + g] = vkeep;
        v1 = v1n;

        // ================= critical: soc chain for step t =================
        float hn[8];
#pragma unroll
        for (int k = 0; k < 8; ++k) {
            float pre = fmaf(It, w1[k], fmaf(Tt, w2[k], wb[k]));
            hn[k] = tanh_fast(fmaf(soc, w0[k], pre));
        }
        // Q partial (tree), 1 butterfly stage + 8-lane gather + add tree
        float t0 = fmaf(hn[0], wq[0], bq16);
        float t1 = hn[1] * wq[1];
        float t2 = hn[2] * wq[2];
        float t3 = hn[3] * wq[3];
        float t4 = hn[4] * wq[4];
        float t5 = hn[5] * wq[5];
        float t6 = hn[6] * wq[6];
        float t7 = hn[7] * wq[7];
        float p3 = ((t0 + t1) + (t2 + t3)) + ((t4 + t5) + (t6 + t7));
        p3 += __shfl_xor_sync(0xffffffffu, p3, 1);           // pairs done
        float r0g = __shfl_sync(0xffffffffu, p3, half | 0);
        float r1g = __shfl_sync(0xffffffffu, p3, half | 2);
        float r2g = __shfl_sync(0xffffffffu, p3, half | 4);
        float r3g = __shfl_sync(0xffffffffu, p3, half | 6);
        float r4g = __shfl_sync(0xffffffffu, p3, half | 8);
        float r5g = __shfl_sync(0xffffffffu, p3, half | 10);
        float r6g = __shfl_sync(0xffffffffu, p3, half | 12);
        float r7g = __shfl_sync(0xffffffffu, p3, half | 14);
        float s3 = ((r0g + r1g) + (r2g + r3g)) + ((r4g + r5g) + (r6g + r7g));

        float Q    = fmaf(sp_pre(s3), 5.0f * LN2, EPS);
        float rq   = rcp_fast(Q);
        float socn = __saturatef(fmaf(cIt, rq, soc));

        // rotate pipeline state
#pragma unroll
        for (int k = 0; k < 8; ++k) h[k] = hn[k];
        socInP = soc; IP = It; TP = Tt;
        soc = socn;
        It = In; Tt = Tn; cIt = In * (-1.0f / 3600.0f);
    }

    // ================= epilogue: V_pred for t = 1023 =================
    {
        float p0 = fmaf(h[0], wx[0], bx16);
        float p1 = fmaf(h[0], wy[0], by16);
        float p2 = fmaf(h[0], wz[0], bz16);
#pragma unroll
        for (int k = 1; k < 8; ++k) {
            p0 = fmaf(h[k], wx[k], p0);
            p1 = fmaf(h[k], wy[k], p1);
            p2 = fmaf(h[k], wz[k], p2);
        }
        float pr = br16;
#pragma unroll
        for (int k = 0; k < 4; ++k) {
            float pre = fmaf(IP, q1[k], fmaf(TP, q2[k], qb[k]));
            float hrk = tanh_fast(fmaf(socInP, q0[k], pre));
            pr = fmaf(hrk, qw[k], pr);
        }
#pragma unroll
        for (int d = 1; d <= 8; d <<= 1) {
            p0 += __shfl_xor_sync(0xffffffffu, p0, d);
            p1 += __shfl_xor_sync(0xffffffffu, p1, d);
            p2 += __shfl_xor_sync(0xffffffffu, p2, d);
            pr += __shfl_xor_sync(0xffffffffu, pr, d);
        }
        float R0 = fmaf(sp_pre(p0), 0.01f   * LN2, EPS);
        float R1 = fmaf(sp_pre(p1), 0.02f   * LN2, EPS);
        float C1 = fmaf(sp_pre(p2), 2000.0f * LN2, EPS);
        float invRC = rcp_fast(R1 * C1);
        float invC1 = invRC * R1;
        float v1n = fmaf(IP, invC1, fmaf(-v1, invRC, v1));
        float ocv = fmaf(fmaf(fmaf(0.3f, soc, -0.5f), soc, 1.2f), soc, 3.0f);
        float Vp  = (ocv - fmaf(IP, R0, v1n)) + pr;
        if (15 == g) vkeep = Vp;                 // tp=1023: tp&15==15
        orow[1008 + g] = vkeep;
    }
}

extern "C" void kernel_launch(void* const* d_in, const int* in_sizes, int n_in,
                              void* d_out, int out_size)
{
    // inputs: V(unused), I, Tz, soc0, W1p, b1p, W2p, b2p, W1r, b1r, W2r, b2r
    const float* I    = (const float*)d_in[1];
    const float* Tz   = (const float*)d_in[2];
    const float* soc0 = (const float*)d_in[3];
    const float* W1p  = (const float*)d_in[4];
    const float* b1p  = (const float*)d_in[5];
    const float* W2p  = (const float*)d_in[6];
    const float* b2p  = (const float*)d_in[7];
    const float* W1r  = (const float*)d_in[8];
    const float* b1r  = (const float*)d_in[9];
    const float* W2r  = (const float*)d_in[10];
    const float* b2r  = (const float*)d_in[11];
    float* out = (float*)d_out;

    // 512 warps = 1024 batteries (2/warp); 128 blocks x 128 threads
    // -> 1 block/SM, exactly 1 warp per SMSP.
    dci_rollout<<<128, 128>>>(I, Tz, soc0, W1p, b1p, W2p, b2p,
                              W1r, b1r, W2r, b2r, out);
}

// round 5
// speedup vs baseline: 1.0668x; 1.0611x over previous
#include <cuda_runtime.h>

namespace {
constexpr int Hn = 1024;   // time steps

__device__ __forceinline__ float tanh_fast(float x){ float r; asm("tanh.approx.f32 %0, %1;" : "=f"(r) : "f"(x)); return r; }
__device__ __forceinline__ float ex2_fast (float x){ float r; asm("ex2.approx.ftz.f32 %0, %1;" : "=f"(r) : "f"(x)); return r; }
__device__ __forceinline__ float lg2_fast (float x){ float r; asm("lg2.approx.ftz.f32 %0, %1;" : "=f"(r) : "f"(x)); return r; }
__device__ __forceinline__ float rcp_fast (float x){ float r; asm("rcp.approx.ftz.f32 %0, %1;" : "=f"(r) : "f"(x)); return r; }
// softplus given pre-scaled (log2e) argument: log2(1 + 2^y)
__device__ __forceinline__ float sp_pre(float y){ return lg2_fast(1.0f + ex2_fast(y)); }
}

// 2 batteries per warp; 16 lanes per battery. Lane g owns hp units {g+16k, k<8},
// hr units {g+16k, k<4}. Software-pipelined with explicit issue staging:
//   [off butterflies on h_{t-1}] -> [critical tanh/Q chain for t] ->
//   [critical softplus/rcp] -> [off consumers: params, v1, V_pred(t-1), store]
__global__ void __launch_bounds__(128, 1) dci_rollout(
    const float* __restrict__ gI, const float* __restrict__ gT, const float* __restrict__ soc0,
    const float* __restrict__ W1p, const float* __restrict__ b1p,
    const float* __restrict__ W2p, const float* __restrict__ b2p,
    const float* __restrict__ W1r, const float* __restrict__ b1r,
    const float* __restrict__ W2r, const float* __restrict__ b2r,
    float* __restrict__ out)
{
    const int tid  = blockIdx.x * blockDim.x + threadIdx.x;
    const int lane = threadIdx.x & 31;
    const int g    = lane & 15;
    const int half = lane & 16;
    const int bat  = (tid >> 5) * 2 + (lane >> 4);

    constexpr float LOG2E = 1.4426950408889634f;
    constexpr float LN2   = 0.6931471805599453f;
    constexpr float EPS   = 1e-6f;

    // --- weights into registers (one-time); W2 columns pre-scaled by log2e ---
    float w0[8], w1[8], w2[8], wb[8];
    float wx[8], wy[8], wz[8], wq[8];
#pragma unroll
    for (int k = 0; k < 8; ++k) {
        int u = g + 16 * k;
        w0[k] = W1p[u]; w1[k] = W1p[128 + u]; w2[k] = W1p[256 + u]; wb[k] = b1p[u];
        float4 wp = reinterpret_cast<const float4*>(W2p)[u];   // [R0,R1,C1,Q] row u
        wx[k] = wp.x * LOG2E; wy[k] = wp.y * LOG2E; wz[k] = wp.z * LOG2E; wq[k] = wp.w * LOG2E;
    }
    float q0[4], q1[4], q2[4], qb[4], qw[4];
#pragma unroll
    for (int k = 0; k < 4; ++k) {
        int u = g + 16 * k;
        q0[k] = W1r[u]; q1[k] = W1r[64 + u]; q2[k] = W1r[128 + u]; qb[k] = b1r[u];
        qw[k] = W2r[u];
    }
    float4 b2 = *reinterpret_cast<const float4*>(b2p);
    // biases pre-scaled by log2e, divided by 16 (folded into each lane's partial)
    const float bx16 = b2.x * (LOG2E / 16.0f);
    const float by16 = b2.y * (LOG2E / 16.0f);
    const float bz16 = b2.z * (LOG2E / 16.0f);
    const float bq16 = b2.w * (LOG2E / 16.0f);
    const float br16 = b2r[0] * (1.0f / 16.0f);

    float s0  = soc0[bat];
    float soc = (s0 == s0) ? s0 : 0.8f;   // NaN -> 0.8
    float v1  = 0.0f;

    const float* Ib = gI + bat * Hn;
    const float* Tb = gT + bat * Hn;
    float It  = __ldg(Ib), Tt = __ldg(Tb);
    float cIt = It * (-1.0f / 3600.0f);
    float vkeep = 0.0f;
    float* orow = out + bat * Hn;

    // pipeline state for the deferred (t-1) V_pred work
    float hA[8], hB[8];
#pragma unroll
    for (int k = 0; k < 8; ++k) { hA[k] = 0.0f; hB[k] = 0.0f; }
    float socInP = 0.0f, IP = 0.0f, TP = 0.0f;

    // one pipelined step: consumes hP (h of step t-1), produces hN (h of step t)
    auto body = [&](float* hP, float* hN, int t) {
        const int tn = (t + 1) & (Hn - 1);      // wrap: harmless in-bounds load
        const float In = __ldg(Ib + tn);
        const float Tn = __ldg(Tb + tn);

        // ---- (1) off partials from h_{t-1}: ready at iteration start ----
        float p0 = fmaf(hP[0], wx[0], bx16);
        float p1 = fmaf(hP[0], wy[0], by16);
        float p2 = fmaf(hP[0], wz[0], bz16);
#pragma unroll
        for (int k = 1; k < 8; ++k) {
            p0 = fmaf(hP[k], wx[k], p0);
            p1 = fmaf(hP[k], wy[k], p1);
            p2 = fmaf(hP[k], wz[k], p2);
        }
        // ---- (2) off butterflies: issue-only, latency hides under tanh ----
#pragma unroll
        for (int d = 1; d <= 8; d <<= 1) {
            p0 += __shfl_xor_sync(0xffffffffu, p0, d);
            p1 += __shfl_xor_sync(0xffffffffu, p1, d);
            p2 += __shfl_xor_sync(0xffffffffu, p2, d);
        }

        // ---- (3) critical: preact + 8 tanh (MUFU first!) ----
#pragma unroll
        for (int k = 0; k < 8; ++k) {
            float pre = fmaf(It, w1[k], fmaf(Tt, w2[k], wb[k]));
            hN[k] = tanh_fast(fmaf(soc, w0[k], pre));
        }

        // ---- (4) hr head (prev inputs) — MUFU behind the critical tanhs ----
        float pr = br16;
#pragma unroll
        for (int k = 0; k < 4; ++k) {
            float pre = fmaf(IP, q1[k], fmaf(TP, q2[k], qb[k]));
            float hrk = tanh_fast(fmaf(socInP, q0[k], pre));
            pr = fmaf(hrk, qw[k], pr);
        }

        // ---- (5) critical: Q tree + reduce (xor1 + 8-lane gather) ----
        float t0 = fmaf(hN[0], wq[0], bq16);
        float t1 = hN[1] * wq[1];
        float t2 = hN[2] * wq[2];
        float t3 = hN[3] * wq[3];
        float t4 = hN[4] * wq[4];
        float t5 = hN[5] * wq[5];
        float t6 = hN[6] * wq[6];
        float t7 = hN[7] * wq[7];
        float p3 = ((t0 + t1) + (t2 + t3)) + ((t4 + t5) + (t6 + t7));
        p3 += __shfl_xor_sync(0xffffffffu, p3, 1);
        float r0g = __shfl_sync(0xffffffffu, p3, half | 0);
        float r1g = __shfl_sync(0xffffffffu, p3, half | 2);
        float r2g = __shfl_sync(0xffffffffu, p3, half | 4);
        float r3g = __shfl_sync(0xffffffffu, p3, half | 6);
        float r4g = __shfl_sync(0xffffffffu, p3, half | 8);
        float r5g = __shfl_sync(0xffffffffu, p3, half | 10);
        float r6g = __shfl_sync(0xffffffffu, p3, half | 12);
        float r7g = __shfl_sync(0xffffffffu, p3, half | 14);

        // ---- (6) pr butterflies issue under the gather latency ----
#pragma unroll
        for (int d = 1; d <= 8; d <<= 1)
            pr += __shfl_xor_sync(0xffffffffu, pr, d);

        float s3 = ((r0g + r1g) + (r2g + r3g)) + ((r4g + r5g) + (r6g + r7g));

        // ---- (7) critical: softplus -> Q -> rcp -> soc update ----
        float Q    = fmaf(sp_pre(s3), 5.0f * LN2, EPS);
        float rq   = rcp_fast(Q);
        float socn = __saturatef(fmaf(cIt, rq, soc));

        // ---- (8) off consumers: params, v1, V_pred(t-1), store ----
        float R0 = fmaf(sp_pre(p0), 0.01f   * LN2, EPS);
        float R1 = fmaf(sp_pre(p1), 0.02f   * LN2, EPS);
        float C1 = fmaf(sp_pre(p2), 2000.0f * LN2, EPS);
        float invRC = rcp_fast(R1 * C1);
        float invC1 = invRC * R1;                            // 1/C1 = R1/(R1*C1)
        float v1n = fmaf(IP, invC1, fmaf(-v1, invRC, v1));   // v1 - v1/(R1C1) + I/C1
        float ocv = fmaf(fmaf(fmaf(0.3f, soc, -0.5f), soc, 1.2f), soc, 3.0f);
        float Vp  = (ocv - fmaf(IP, R0, v1n)) + pr;          // ocv - I*R0 - v1 + resid

        const int tp = t - 1;
        if ((tp & 15) == g)            vkeep = Vp;
        if (t > 0 && (tp & 15) == 15)  orow[(tp & ~15) + g] = vkeep;  // guard t=0 (OOB!)
        v1 = v1n;

        // ---- (9) rotate scalar state ----
        socInP = soc; IP = It; TP = Tt;
        soc = socn;
        It = In; Tt = Tn; cIt = In * (-1.0f / 3600.0f);
    };

#pragma unroll 1
    for (int t = 0; t < Hn; t += 2) {
        body(hA, hB, t);
        body(hB, hA, t + 1);
    }

    // ================= epilogue: V_pred for t = 1023 (h in hA) =================
    {
        float p0 = fmaf(hA[0], wx[0], bx16);
        float p1 = fmaf(hA[0], wy[0], by16);
        float p2 = fmaf(hA[0], wz[0], bz16);
#pragma unroll
        for (int k = 1; k < 8; ++k) {
            p0 = fmaf(hA[k], wx[k], p0);
            p1 = fmaf(hA[k], wy[k], p1);
            p2 = fmaf(hA[k], wz[k], p2);
        }
        float pr = br16;
#pragma unroll
        for (int k = 0; k < 4; ++k) {
            float pre = fmaf(IP, q1[k], fmaf(TP, q2[k], qb[k]));
            float hrk = tanh_fast(fmaf(socInP, q0[k], pre));
            pr = fmaf(hrk, qw[k], pr);
        }
#pragma unroll
        for (int d = 1; d <= 8; d <<= 1) {
            p0 += __shfl_xor_sync(0xffffffffu, p0, d);
            p1 += __shfl_xor_sync(0xffffffffu, p1, d);
            p2 += __shfl_xor_sync(0xffffffffu, p2, d);
            pr += __shfl_xor_sync(0xffffffffu, pr, d);
        }
        float R0 = fmaf(sp_pre(p0), 0.01f   * LN2, EPS);
        float R1 = fmaf(sp_pre(p1), 0.02f   * LN2, EPS);
        float C1 = fmaf(sp_pre(p2), 2000.0f * LN2, EPS);
        float invRC = rcp_fast(R1 * C1);
        float invC1 = invRC * R1;
        float v1n = fmaf(IP, invC1, fmaf(-v1, invRC, v1));
        float ocv = fmaf(fmaf(fmaf(0.3f, soc, -0.5f), soc, 1.2f), soc, 3.0f);
        float Vp  = (ocv - fmaf(IP, R0, v1n)) + pr;
        if (g == 15) vkeep = Vp;                 // tp=1023: tp&15==15
        orow[1008 + g] = vkeep;
    }
}

extern "C" void kernel_launch(void* const* d_in, const int* in_sizes, int n_in,
                              void* d_out, int out_size)
{
    // inputs: V(unused), I, Tz, soc0, W1p, b1p, W2p, b2p, W1r, b1r, W2r, b2r
    const float* I    = (const float*)d_in[1];
    const float* Tz   = (const float*)d_in[2];
    const float* soc0 = (const float*)d_in[3];
    const float* W1p  = (const float*)d_in[4];
    const float* b1p  = (const float*)d_in[5];
    const float* W2p  = (const float*)d_in[6];
    const float* b2p  = (const float*)d_in[7];
    const float* W1r  = (const float*)d_in[8];
    const float* b1r  = (const float*)d_in[9];
    const float* W2r  = (const float*)d_in[10];
    const float* b2r  = (const float*)d_in[11];
    float* out = (float*)d_out;

    // 512 warps = 1024 batteries (2/warp); 128 blocks x 128 threads
    // -> 1 block/SM, exactly 1 warp per SMSP.
    dci_rollout<<<128, 128>>>(I, Tz, soc0, W1p, b1p, W2p, b2p,
                              W1r, b1r, W2r, b2r, out);
}